// round 1
// baseline (speedup 1.0000x reference)
#include <cuda_runtime.h>
#include <math.h>

#define NN_MAX 100000
#define EE_MAX 1600000
#define DF 128

// ---------------- scratch (device globals: no allocation allowed) ----------------
__device__ int   g_idx64;
__device__ int   g_cnt[NN_MAX];
__device__ int   g_rowptr[NN_MAX + 1];
__device__ int   g_cursor[NN_MAX];
__device__ int   g_srcs[EE_MAX];
__device__ float g_dinv[NN_MAX];
__device__ float g_z0[(size_t)NN_MAX * DF];
__device__ float g_z1[(size_t)NN_MAX * DF];
__device__ float g_zs[(size_t)NN_MAX * DF];
__device__ float g_W2pad[DF * DF];
__device__ float g_b2pad[DF];
__device__ float g_zerob[DF];   // stays zero (bss)

// ---------------- helpers ----------------
__device__ __forceinline__ long long ldidx(const void* p, long long i, int is64) {
    return is64 ? ((const long long*)p)[i] : (long long)(((const int*)p)[i]);
}

// Detect whether edge_index was serialized as int64 (upper 32-bit words all zero)
__global__ void k_detect(const void* ei, long long E) {
    const unsigned* w = (const unsigned*)ei;
    int lim = (int)(E - 1 < 1024 ? E - 1 : 1024);
    unsigned acc = 0;
    for (int i = 0; i < lim; i++) acc |= w[2 * i + 1];
    g_idx64 = (acc == 0u) ? 1 : 0;
}

__global__ void k_init(int n) {
    int i = blockIdx.x * blockDim.x + threadIdx.x;
    if (i < n) g_cnt[i] = 0;
}

__global__ void k_count(const void* ei, long long E) {
    int is64 = g_idx64;
    long long stride = (long long)gridDim.x * blockDim.x;
    for (long long e = (long long)blockIdx.x * blockDim.x + threadIdx.x; e < E; e += stride) {
        int dst = (int)ldidx(ei, E + e, is64);  // second row = targets
        atomicAdd(&g_cnt[dst], 1);
    }
}

// Single-block exclusive scan over g_cnt -> g_rowptr / g_cursor, plus dinv
__global__ void k_scan(int n) {
    __shared__ int sm[1024];
    int tid = threadIdx.x;
    int C = (n + 1 + 1023) / 1024;
    int base = tid * C;
    int s = 0;
    for (int i = 0; i < C; i++) {
        int idx = base + i;
        if (idx < n) s += g_cnt[idx];
    }
    sm[tid] = s;
    __syncthreads();
    for (int d = 1; d < 1024; d <<= 1) {
        int t = (tid >= d) ? sm[tid - d] : 0;
        __syncthreads();
        sm[tid] += t;
        __syncthreads();
    }
    int run = sm[tid] - s;  // exclusive prefix
    for (int i = 0; i < C; i++) {
        int idx = base + i;
        if (idx <= n) {
            g_rowptr[idx] = run;
            if (idx < n) {
                g_cursor[idx] = run;
                g_dinv[idx] = rsqrtf((float)(g_cnt[idx] + 1));  // +1 self loop
                run += g_cnt[idx];
            }
        }
    }
}

__global__ void k_fill(const void* ei, long long E) {
    int is64 = g_idx64;
    long long stride = (long long)gridDim.x * blockDim.x;
    for (long long e = (long long)blockIdx.x * blockDim.x + threadIdx.x; e < E; e += stride) {
        int src = (int)ldidx(ei, e, is64);
        int dst = (int)ldidx(ei, E + e, is64);
        int p = atomicAdd(&g_cursor[dst], 1);
        g_srcs[p] = src;
    }
}

// ---------------- SGEMM: C[M,128] = A[M,128] @ W[128,128]^T + bias, opt activation ----------------
// ACT: 0 = none, 1 = ELU
#define BM 128
#define BN 128
#define BKK 8
#define TM 8
#define TN 8

__device__ __forceinline__ float act_apply(float v, int ACT) {
    if (ACT == 1) return v > 0.f ? v : expm1f(v);
    return v;
}

template <int ACT>
__global__ __launch_bounds__(256) void k_gemm128(
    const float* __restrict__ A, const float* __restrict__ W,
    const float* __restrict__ bias, float* __restrict__ C, int M) {
    __shared__ float As[BKK][BM];
    __shared__ float Bs[BKK][BN];
    int tid = threadIdx.x;
    int rowBase = blockIdx.x * BM;
    int threadCol = tid % 16;
    int threadRow = tid / 16;
    int aRow = tid / 2;
    int aCol = (tid % 2) * 4;
    int bRow = tid / 2;          // output-feature row of W
    int bCol = (tid % 2) * 4;    // k
    float acc[TM][TN];
#pragma unroll
    for (int i = 0; i < TM; i++)
#pragma unroll
        for (int j = 0; j < TN; j++) acc[i][j] = 0.f;

    for (int k0 = 0; k0 < DF; k0 += BKK) {
        int gRow = rowBase + aRow;
        float4 av = make_float4(0.f, 0.f, 0.f, 0.f);
        if (gRow < M) av = *(const float4*)(A + (size_t)gRow * DF + k0 + aCol);
        As[aCol + 0][aRow] = av.x;
        As[aCol + 1][aRow] = av.y;
        As[aCol + 2][aRow] = av.z;
        As[aCol + 3][aRow] = av.w;
        float4 bv = *(const float4*)(W + (size_t)bRow * DF + k0 + bCol);
        Bs[bCol + 0][bRow] = bv.x;
        Bs[bCol + 1][bRow] = bv.y;
        Bs[bCol + 2][bRow] = bv.z;
        Bs[bCol + 3][bRow] = bv.w;
        __syncthreads();
#pragma unroll
        for (int kk = 0; kk < BKK; kk++) {
            float rm[TM], rn[TN];
            *(float4*)&rm[0] = *(const float4*)&As[kk][threadRow * TM];
            *(float4*)&rm[4] = *(const float4*)&As[kk][threadRow * TM + 4];
            *(float4*)&rn[0] = *(const float4*)&Bs[kk][threadCol * TN];
            *(float4*)&rn[4] = *(const float4*)&Bs[kk][threadCol * TN + 4];
#pragma unroll
            for (int i = 0; i < TM; i++)
#pragma unroll
                for (int j = 0; j < TN; j++) acc[i][j] = fmaf(rm[i], rn[j], acc[i][j]);
        }
        __syncthreads();
    }

    float bb[TN];
#pragma unroll
    for (int j = 0; j < TN; j++) bb[j] = bias[threadCol * TN + j];

#pragma unroll
    for (int i = 0; i < TM; i++) {
        int r = rowBase + threadRow * TM + i;
        if (r < M) {
            float4 v0, v1;
            v0.x = act_apply(acc[i][0] + bb[0], ACT);
            v0.y = act_apply(acc[i][1] + bb[1], ACT);
            v0.z = act_apply(acc[i][2] + bb[2], ACT);
            v0.w = act_apply(acc[i][3] + bb[3], ACT);
            v1.x = act_apply(acc[i][4] + bb[4], ACT);
            v1.y = act_apply(acc[i][5] + bb[5], ACT);
            v1.z = act_apply(acc[i][6] + bb[6], ACT);
            v1.w = act_apply(acc[i][7] + bb[7], ACT);
            float* cp = C + (size_t)r * DF + threadCol * TN;
            *(float4*)(cp + 0) = v0;
            *(float4*)(cp + 4) = v1;
        }
    }
}

// ---------------- aggregation: out[i] = dinv[i]^2*z[i] + sum_e dinv[i]*dinv[src]*z[src] + bias ----------------
__global__ void k_agg(const float* __restrict__ zin, float* __restrict__ zout,
                      const float* __restrict__ bias, int n, int relu) {
    int w = (blockIdx.x * blockDim.x + threadIdx.x) >> 5;
    int lane = threadIdx.x & 31;
    if (w >= n) return;
    float di = g_dinv[w];
    const float4* zi = (const float4*)zin;
    float4 a = zi[(size_t)w * 32 + lane];
    float sw = di * di;
    float4 acc;
    acc.x = sw * a.x; acc.y = sw * a.y; acc.z = sw * a.z; acc.w = sw * a.w;
    int beg = g_rowptr[w], end = g_rowptr[w + 1];
    for (int e = beg; e < end; e++) {
        int s = g_srcs[e];
        float wt = di * g_dinv[s];
        float4 v = zi[(size_t)s * 32 + lane];
        acc.x = fmaf(wt, v.x, acc.x);
        acc.y = fmaf(wt, v.y, acc.y);
        acc.z = fmaf(wt, v.z, acc.z);
        acc.w = fmaf(wt, v.w, acc.w);
    }
    float4 b = ((const float4*)bias)[lane];
    acc.x += b.x; acc.y += b.y; acc.z += b.z; acc.w += b.w;
    if (relu) {
        acc.x = fmaxf(acc.x, 0.f); acc.y = fmaxf(acc.y, 0.f);
        acc.z = fmaxf(acc.z, 0.f); acc.w = fmaxf(acc.w, 0.f);
    }
    ((float4*)zout)[(size_t)w * 32 + lane] = acc;
}

// pad fcW2 [64,128] -> [128,128] (zeros below), fcb2 -> 128
__global__ void k_pad(const float* __restrict__ fcW2, const float* __restrict__ fcb2) {
    int i = blockIdx.x * blockDim.x + threadIdx.x;
    if (i < DF * DF) {
        int r = i >> 7, c = i & 127;
        g_W2pad[i] = (r < 64) ? fcW2[r * DF + c] : 0.f;
    }
    if (i < DF) g_b2pad[i] = (i < 64) ? fcb2[i] : 0.f;
}

// log_softmax over 64 logits (stored at row stride 128 in scratch)
__global__ void k_lsm(const float* __restrict__ logits, float* __restrict__ out, int n) {
    int w = (blockIdx.x * blockDim.x + threadIdx.x) >> 5;
    int lane = threadIdx.x & 31;
    if (w >= n) return;
    const float* r = logits + (size_t)w * DF;
    float a = r[lane], b = r[lane + 32];
    float m = fmaxf(a, b);
#pragma unroll
    for (int d = 16; d; d >>= 1) m = fmaxf(m, __shfl_xor_sync(0xffffffffu, m, d));
    float se = expf(a - m) + expf(b - m);
#pragma unroll
    for (int d = 16; d; d >>= 1) se += __shfl_xor_sync(0xffffffffu, se, d);
    float ls = m + logf(se);
    out[(size_t)w * 64 + lane] = a - ls;
    out[(size_t)w * 64 + lane + 32] = b - ls;
}

// ---------------- launcher ----------------
extern "C" void kernel_launch(void* const* d_in, const int* in_sizes, int n_in,
                              void* d_out, int out_size) {
    const float* x    = (const float*)d_in[0];
    const void*  ei   = d_in[1];
    const float* W1   = (const float*)d_in[2];
    const float* b1   = (const float*)d_in[3];
    const float* W2   = (const float*)d_in[4];
    const float* b2   = (const float*)d_in[5];
    const float* fcW1 = (const float*)d_in[6];
    const float* fcb1 = (const float*)d_in[7];
    const float* fcW2 = (const float*)d_in[8];
    const float* fcb2 = (const float*)d_in[9];

    int N = in_sizes[0] / DF;
    long long E = (long long)in_sizes[1] / 2;

    float *z0, *z1, *zsb, *w2p, *b2p, *zb;
    cudaGetSymbolAddress((void**)&z0,  g_z0);
    cudaGetSymbolAddress((void**)&z1,  g_z1);
    cudaGetSymbolAddress((void**)&zsb, g_zs);
    cudaGetSymbolAddress((void**)&w2p, g_W2pad);
    cudaGetSymbolAddress((void**)&b2p, g_b2pad);
    cudaGetSymbolAddress((void**)&zb,  g_zerob);

    // Output layout: tuple (zs [N,128], res [N,64]) concatenated.
    float* zs_out;
    float* res_out;
    long long need_both = (long long)N * (DF + 64);
    if ((long long)out_size >= need_both) {
        zs_out = (float*)d_out;
        res_out = (float*)d_out + (size_t)N * DF;
    } else if (out_size == N * 64) {
        zs_out = zsb;               // zs goes to scratch, only res requested
        res_out = (float*)d_out;
    } else {
        zs_out = (float*)d_out;     // zs only
        res_out = zsb;
    }

    int nb_n  = (N + 255) / 256;
    int nb_e  = (int)((E + 255) / 256);
    int nb_w  = (N * 32 + 255) / 256;   // warp-per-node grids
    int nb_g  = (N + BM - 1) / BM;

    // graph preprocessing (rebuilt every launch: no caching allowed)
    k_detect<<<1, 1>>>(ei, E);
    k_init<<<nb_n, 256>>>(N);
    k_count<<<nb_e, 256>>>(ei, E);
    k_scan<<<1, 1024>>>(N);
    k_fill<<<nb_e, 256>>>(ei, E);

    // layer 1: z1 = relu(agg(x @ W1^T) + b1)
    k_gemm128<0><<<nb_g, 256>>>(x, W1, zb, z0, N);
    k_agg<<<nb_w, 256>>>(z0, z1, b1, N, 1);

    // layer 2: zs = agg(z1 @ W2^T) + b2   (first output)
    k_gemm128<0><<<nb_g, 256>>>(z1, W2, zb, z0, N);
    k_agg<<<nb_w, 256>>>(z0, zs_out, b2, N, 0);

    // projection MLP: h = elu(zs @ fcW1^T + fcb1); logits = h @ fcW2pad^T + fcb2pad
    k_pad<<<64, 256>>>(fcW2, fcb2);
    k_gemm128<1><<<nb_g, 256>>>(zs_out, fcW1, fcb1, z1, N);
    k_gemm128<0><<<nb_g, 256>>>(z1, w2p, b2p, z0, N);

    // res = log_softmax(logits[:, :64])   (second output)
    k_lsm<<<nb_w, 256>>>(z0, res_out, N);
}

// round 2
// speedup vs baseline: 1.4034x; 1.4034x over previous
#include <cuda_runtime.h>
#include <math.h>

#define NN_MAX 100000
#define EE_MAX 1600000
#define DF 128

#define SCAN_T 256
#define SCAN_C 4
#define SCAN_TILE (SCAN_T * SCAN_C)          // 1024 elems per block
#define SCAN_NBMAX ((NN_MAX + 1 + SCAN_TILE - 1) / SCAN_TILE + 1)

// ---------------- scratch (device globals: no allocation allowed) ----------------
__device__ int   g_idx64;
__device__ int   g_cnt[NN_MAX];
__device__ int   g_rowptr[NN_MAX + 1];
__device__ int   g_cursor[NN_MAX];
__device__ int   g_srcs[EE_MAX];
__device__ float g_dinv[NN_MAX];
__device__ int   g_bsum[SCAN_NBMAX];
__device__ int   g_boff[SCAN_NBMAX];
__device__ float g_z0[(size_t)NN_MAX * DF];
__device__ float g_z1[(size_t)NN_MAX * DF];
__device__ float g_zs[(size_t)NN_MAX * DF];
__device__ float g_W2pad[DF * DF];
__device__ float g_b2pad[DF];
__device__ float g_zerob[DF];   // stays zero (bss)

// ---------------- helpers ----------------
__device__ __forceinline__ long long ldidx(const void* p, long long i, int is64) {
    return is64 ? ((const long long*)p)[i] : (long long)(((const int*)p)[i]);
}

// Detect whether edge_index was serialized as int64 (upper words of first 1024 entries all zero)
__global__ void k_detect(const void* ei, long long E) {
    __shared__ unsigned sm[256];
    const unsigned* w = (const unsigned*)ei;
    int tid = threadIdx.x;
    int lim = (int)(E - 1 < 1024 ? E - 1 : 1024);
    unsigned acc = 0;
    for (int i = tid; i < lim; i += 256) acc |= w[2 * i + 1];
    sm[tid] = acc;
    __syncthreads();
    for (int d = 128; d; d >>= 1) {
        if (tid < d) sm[tid] |= sm[tid + d];
        __syncthreads();
    }
    if (tid == 0) g_idx64 = (sm[0] == 0u) ? 1 : 0;
}

__global__ void k_init(int n) {
    int i = blockIdx.x * blockDim.x + threadIdx.x;
    if (i < n) g_cnt[i] = 0;
}

__global__ void k_count(const void* ei, long long E) {
    int is64 = g_idx64;
    long long stride = (long long)gridDim.x * blockDim.x;
    for (long long e = (long long)blockIdx.x * blockDim.x + threadIdx.x; e < E; e += stride) {
        int dst = (int)ldidx(ei, E + e, is64);  // second row = targets
        atomicAdd(&g_cnt[dst], 1);
    }
}

// ---------------- 3-phase chip-wide exclusive scan of g_cnt ----------------
// Phase A: per-block partial sums
__global__ void k_scan_a(int n) {
    __shared__ int sm[SCAN_T];
    int tid = threadIdx.x;
    int base = blockIdx.x * SCAN_TILE + tid * SCAN_C;
    int s = 0;
#pragma unroll
    for (int i = 0; i < SCAN_C; i++) {
        int idx = base + i;
        if (idx < n) s += g_cnt[idx];
    }
    sm[tid] = s;
    __syncthreads();
    for (int d = SCAN_T / 2; d; d >>= 1) {
        if (tid < d) sm[tid] += sm[tid + d];
        __syncthreads();
    }
    if (tid == 0) g_bsum[blockIdx.x] = sm[0];
}

// Phase B: exclusive scan over nb block sums (nb <= SCAN_NBMAX <= 128)
__global__ void k_scan_b(int nb) {
    __shared__ int sm[128];
    int tid = threadIdx.x;
    int v = (tid < nb) ? g_bsum[tid] : 0;
    sm[tid] = v;
    __syncthreads();
    for (int d = 1; d < 128; d <<= 1) {
        int t = (tid >= d) ? sm[tid - d] : 0;
        __syncthreads();
        sm[tid] += t;
        __syncthreads();
    }
    if (tid < nb) g_boff[tid] = sm[tid] - v;  // exclusive
}

// Phase C: per-block re-scan + writeback of rowptr/cursor/dinv (+rowptr[n])
__global__ void k_scan_c(int n) {
    __shared__ int sm[SCAN_T];
    int tid = threadIdx.x;
    int base = blockIdx.x * SCAN_TILE + tid * SCAN_C;
    int c[SCAN_C];
    int s = 0;
#pragma unroll
    for (int i = 0; i < SCAN_C; i++) {
        int idx = base + i;
        c[i] = (idx < n) ? g_cnt[idx] : 0;
        s += c[i];
    }
    sm[tid] = s;
    __syncthreads();
    for (int d = 1; d < SCAN_T; d <<= 1) {
        int t = (tid >= d) ? sm[tid - d] : 0;
        __syncthreads();
        sm[tid] += t;
        __syncthreads();
    }
    int run = g_boff[blockIdx.x] + sm[tid] - s;  // exclusive prefix for this thread
#pragma unroll
    for (int i = 0; i < SCAN_C; i++) {
        int idx = base + i;
        if (idx < n) {
            g_rowptr[idx] = run;
            g_cursor[idx] = run;
            g_dinv[idx] = rsqrtf((float)(c[i] + 1));  // +1 self loop
            run += c[i];
        } else if (idx == n) {
            g_rowptr[n] = run;
        }
    }
}

__global__ void k_fill(const void* ei, long long E) {
    int is64 = g_idx64;
    long long stride = (long long)gridDim.x * blockDim.x;
    for (long long e = (long long)blockIdx.x * blockDim.x + threadIdx.x; e < E; e += stride) {
        int src = (int)ldidx(ei, e, is64);
        int dst = (int)ldidx(ei, E + e, is64);
        int p = atomicAdd(&g_cursor[dst], 1);
        g_srcs[p] = src;
    }
}

// ---------------- SGEMM: C[M,128] = A[M,128] @ W[128,128]^T + bias, opt activation ----------------
#define BM 128
#define BN 128
#define BKK 8
#define TM 8
#define TN 8

__device__ __forceinline__ float act_apply(float v, int ACT) {
    if (ACT == 1) return v > 0.f ? v : expm1f(v);
    return v;
}

template <int ACT>
__global__ __launch_bounds__(256) void k_gemm128(
    const float* __restrict__ A, const float* __restrict__ W,
    const float* __restrict__ bias, float* __restrict__ C, int M) {
    __shared__ float As[BKK][BM];
    __shared__ float Bs[BKK][BN];
    int tid = threadIdx.x;
    int rowBase = blockIdx.x * BM;
    int threadCol = tid % 16;
    int threadRow = tid / 16;
    int aRow = tid / 2;
    int aCol = (tid % 2) * 4;
    int bRow = tid / 2;          // output-feature row of W
    int bCol = (tid % 2) * 4;    // k
    float acc[TM][TN];
#pragma unroll
    for (int i = 0; i < TM; i++)
#pragma unroll
        for (int j = 0; j < TN; j++) acc[i][j] = 0.f;

    for (int k0 = 0; k0 < DF; k0 += BKK) {
        int gRow = rowBase + aRow;
        float4 av = make_float4(0.f, 0.f, 0.f, 0.f);
        if (gRow < M) av = *(const float4*)(A + (size_t)gRow * DF + k0 + aCol);
        As[aCol + 0][aRow] = av.x;
        As[aCol + 1][aRow] = av.y;
        As[aCol + 2][aRow] = av.z;
        As[aCol + 3][aRow] = av.w;
        float4 bv = *(const float4*)(W + (size_t)bRow * DF + k0 + bCol);
        Bs[bCol + 0][bRow] = bv.x;
        Bs[bCol + 1][bRow] = bv.y;
        Bs[bCol + 2][bRow] = bv.z;
        Bs[bCol + 3][bRow] = bv.w;
        __syncthreads();
#pragma unroll
        for (int kk = 0; kk < BKK; kk++) {
            float rm[TM], rn[TN];
            *(float4*)&rm[0] = *(const float4*)&As[kk][threadRow * TM];
            *(float4*)&rm[4] = *(const float4*)&As[kk][threadRow * TM + 4];
            *(float4*)&rn[0] = *(const float4*)&Bs[kk][threadCol * TN];
            *(float4*)&rn[4] = *(const float4*)&Bs[kk][threadCol * TN + 4];
#pragma unroll
            for (int i = 0; i < TM; i++)
#pragma unroll
                for (int j = 0; j < TN; j++) acc[i][j] = fmaf(rm[i], rn[j], acc[i][j]);
        }
        __syncthreads();
    }

    float bb[TN];
#pragma unroll
    for (int j = 0; j < TN; j++) bb[j] = bias[threadCol * TN + j];

#pragma unroll
    for (int i = 0; i < TM; i++) {
        int r = rowBase + threadRow * TM + i;
        if (r < M) {
            float4 v0, v1;
            v0.x = act_apply(acc[i][0] + bb[0], ACT);
            v0.y = act_apply(acc[i][1] + bb[1], ACT);
            v0.z = act_apply(acc[i][2] + bb[2], ACT);
            v0.w = act_apply(acc[i][3] + bb[3], ACT);
            v1.x = act_apply(acc[i][4] + bb[4], ACT);
            v1.y = act_apply(acc[i][5] + bb[5], ACT);
            v1.z = act_apply(acc[i][6] + bb[6], ACT);
            v1.w = act_apply(acc[i][7] + bb[7], ACT);
            float* cp = C + (size_t)r * DF + threadCol * TN;
            *(float4*)(cp + 0) = v0;
            *(float4*)(cp + 4) = v1;
        }
    }
}

// ---------------- aggregation: out[i] = dinv[i]^2*z[i] + sum_e dinv[i]*dinv[src]*z[src] + bias ----------------
__global__ void k_agg(const float* __restrict__ zin, float* __restrict__ zout,
                      const float* __restrict__ bias, int n, int relu) {
    int w = (blockIdx.x * blockDim.x + threadIdx.x) >> 5;
    int lane = threadIdx.x & 31;
    if (w >= n) return;
    float di = g_dinv[w];
    const float4* zi = (const float4*)zin;
    float4 a = zi[(size_t)w * 32 + lane];
    float sw = di * di;
    float4 acc;
    acc.x = sw * a.x; acc.y = sw * a.y; acc.z = sw * a.z; acc.w = sw * a.w;
    int beg = g_rowptr[w], end = g_rowptr[w + 1];
    for (int e = beg; e < end; e++) {
        int s = g_srcs[e];
        float wt = di * g_dinv[s];
        float4 v = zi[(size_t)s * 32 + lane];
        acc.x = fmaf(wt, v.x, acc.x);
        acc.y = fmaf(wt, v.y, acc.y);
        acc.z = fmaf(wt, v.z, acc.z);
        acc.w = fmaf(wt, v.w, acc.w);
    }
    float4 b = ((const float4*)bias)[lane];
    acc.x += b.x; acc.y += b.y; acc.z += b.z; acc.w += b.w;
    if (relu) {
        acc.x = fmaxf(acc.x, 0.f); acc.y = fmaxf(acc.y, 0.f);
        acc.z = fmaxf(acc.z, 0.f); acc.w = fmaxf(acc.w, 0.f);
    }
    ((float4*)zout)[(size_t)w * 32 + lane] = acc;
}

// pad fcW2 [64,128] -> [128,128] (zeros below), fcb2 -> 128
__global__ void k_pad(const float* __restrict__ fcW2, const float* __restrict__ fcb2) {
    int i = blockIdx.x * blockDim.x + threadIdx.x;
    if (i < DF * DF) {
        int r = i >> 7, c = i & 127;
        g_W2pad[i] = (r < 64) ? fcW2[r * DF + c] : 0.f;
    }
    if (i < DF) g_b2pad[i] = (i < 64) ? fcb2[i] : 0.f;
}

// log_softmax over 64 logits (stored at row stride 128 in scratch)
__global__ void k_lsm(const float* __restrict__ logits, float* __restrict__ out, int n) {
    int w = (blockIdx.x * blockDim.x + threadIdx.x) >> 5;
    int lane = threadIdx.x & 31;
    if (w >= n) return;
    const float* r = logits + (size_t)w * DF;
    float a = r[lane], b = r[lane + 32];
    float m = fmaxf(a, b);
#pragma unroll
    for (int d = 16; d; d >>= 1) m = fmaxf(m, __shfl_xor_sync(0xffffffffu, m, d));
    float se = expf(a - m) + expf(b - m);
#pragma unroll
    for (int d = 16; d; d >>= 1) se += __shfl_xor_sync(0xffffffffu, se, d);
    float ls = m + logf(se);
    out[(size_t)w * 64 + lane] = a - ls;
    out[(size_t)w * 64 + lane + 32] = b - ls;
}

// ---------------- launcher ----------------
extern "C" void kernel_launch(void* const* d_in, const int* in_sizes, int n_in,
                              void* d_out, int out_size) {
    const float* x    = (const float*)d_in[0];
    const void*  ei   = d_in[1];
    const float* W1   = (const float*)d_in[2];
    const float* b1   = (const float*)d_in[3];
    const float* W2   = (const float*)d_in[4];
    const float* b2   = (const float*)d_in[5];
    const float* fcW1 = (const float*)d_in[6];
    const float* fcb1 = (const float*)d_in[7];
    const float* fcW2 = (const float*)d_in[8];
    const float* fcb2 = (const float*)d_in[9];

    int N = in_sizes[0] / DF;
    long long E = (long long)in_sizes[1] / 2;

    float *z0, *z1, *zsb, *w2p, *b2p, *zb;
    cudaGetSymbolAddress((void**)&z0,  g_z0);
    cudaGetSymbolAddress((void**)&z1,  g_z1);
    cudaGetSymbolAddress((void**)&zsb, g_zs);
    cudaGetSymbolAddress((void**)&w2p, g_W2pad);
    cudaGetSymbolAddress((void**)&b2p, g_b2pad);
    cudaGetSymbolAddress((void**)&zb,  g_zerob);

    // Output layout: tuple (zs [N,128], res [N,64]) concatenated.
    float* zs_out;
    float* res_out;
    long long need_both = (long long)N * (DF + 64);
    if ((long long)out_size >= need_both) {
        zs_out = (float*)d_out;
        res_out = (float*)d_out + (size_t)N * DF;
    } else if (out_size == N * 64) {
        zs_out = zsb;               // zs goes to scratch, only res requested
        res_out = (float*)d_out;
    } else {
        zs_out = (float*)d_out;     // zs only
        res_out = zsb;
    }

    int nb_n  = (N + 255) / 256;
    int nb_e  = (int)((E + 255) / 256);
    int nb_w  = (N * 32 + 255) / 256;   // warp-per-node grids
    int nb_g  = (N + BM - 1) / BM;
    int nb_s  = (N + 1 + SCAN_TILE - 1) / SCAN_TILE;   // scan blocks (~98)

    // graph preprocessing (rebuilt every launch: no caching allowed)
    k_detect<<<1, 256>>>(ei, E);
    k_init<<<nb_n, 256>>>(N);
    k_count<<<nb_e, 256>>>(ei, E);
    k_scan_a<<<nb_s, SCAN_T>>>(N);
    k_scan_b<<<1, 128>>>(nb_s);
    k_scan_c<<<nb_s, SCAN_T>>>(N);
    k_fill<<<nb_e, 256>>>(ei, E);

    // layer 1: z1 = relu(agg(x @ W1^T) + b1)
    k_gemm128<0><<<nb_g, 256>>>(x, W1, zb, z0, N);
    k_agg<<<nb_w, 256>>>(z0, z1, b1, N, 1);

    // layer 2: zs = agg(z1 @ W2^T) + b2   (first output)
    k_gemm128<0><<<nb_g, 256>>>(z1, W2, zb, z0, N);
    k_agg<<<nb_w, 256>>>(z0, zs_out, b2, N, 0);

    // projection MLP: h = elu(zs @ fcW1^T + fcb1); logits = h @ fcW2pad^T + fcb2pad
    k_pad<<<64, 256>>>(fcW2, fcb2);
    k_gemm128<1><<<nb_g, 256>>>(zs_out, fcW1, fcb1, z1, N);
    k_gemm128<0><<<nb_g, 256>>>(z1, w2p, b2p, z0, N);

    // res = log_softmax(logits[:, :64])   (second output)
    k_lsm<<<nb_w, 256>>>(z0, res_out, N);
}